// round 7
// baseline (speedup 1.0000x reference)
#include <cuda_runtime.h>
#include <math.h>

#define NN 10000
#define NE 200000
#define HC 320          // HEADS*CONV_DIM = 5*64
#define CD 64
#define ED 16
#define NIT (NE + NN)   // total items = edges + self loops

typedef unsigned long long u64;

// ---------------- device scratch (no allocations allowed) ----------------
__device__ __align__(16) float g_xl[NN * HC];       // per-layer node features [N,320]
__device__ __align__(16) float g_h1[NN * CD];
__device__ __align__(16) float g_h2[NN * CD];
__device__ __align__(16) float g_ea2[(NIT + 32) * ED]; // edge_attr in item order (+loop rows)
__device__ int g_srcs[NIT + 32];                    // src node per item slot
__device__ int g_deg[NN];
__device__ int g_off[NN + 1];                       // CSR offsets (edges only)
__device__ int g_off2[NN + 1];                      // item offsets (edges + self loops)
__device__ int g_cnt[NN];
__device__ int g_csr[NE];

// ---------------- f32x2 helpers ----------------
__device__ __forceinline__ u64 pk2(float lo, float hi) {
    u64 r;
    asm("mov.b64 %0, {%1, %2};" : "=l"(r) : "f"(lo), "f"(hi));
    return r;
}
__device__ __forceinline__ void upk2(u64 v, float& lo, float& hi) {
    asm("mov.b64 {%0, %1}, %2;" : "=f"(lo), "=f"(hi) : "l"(v));
}
__device__ __forceinline__ u64 ffma2(u64 a, u64 b, u64 c) {
    u64 d;
    asm("fma.rn.f32x2 %0, %1, %2, %3;" : "=l"(d) : "l"(a), "l"(b), "l"(c));
    return d;
}
__device__ __forceinline__ u64 fadd2(u64 a, u64 b) {
    u64 d;
    asm("add.rn.f32x2 %0, %1, %2;" : "=l"(d) : "l"(a), "l"(b));
    return d;
}
__device__ __forceinline__ u64 fmul2(u64 a, u64 b) {
    u64 d;
    asm("mul.rn.f32x2 %0, %1, %2;" : "=l"(d) : "l"(a), "l"(b));
    return d;
}
__device__ __forceinline__ float ex2f(float x) {
    float r;
    asm("ex2.approx.f32 %0, %1;" : "=f"(r) : "f"(x));
    return r;
}

// ---------------- preprocessing ----------------
__global__ void k_init() {
    int i = blockIdx.x * blockDim.x + threadIdx.x;
    if (i < NN) g_deg[i] = 0;
}

__global__ void k_deg(const int* __restrict__ ei) {
    int e = blockIdx.x * blockDim.x + threadIdx.x;
    if (e >= NE) return;
    atomicAdd(&g_deg[ei[NE + e]], 1);
}

__global__ void k_scan() {
    __shared__ int sums[1024];
    int t = threadIdx.x;
    const int per = 10;  // 1024*10 >= 10000
    int base = t * per;
    int s = 0;
#pragma unroll
    for (int i = 0; i < per; i++) {
        int idx = base + i;
        if (idx < NN) s += g_deg[idx];
    }
    sums[t] = s;
    __syncthreads();
    for (int off = 1; off < 1024; off <<= 1) {
        int v = 0;
        if (t >= off) v = sums[t - off];
        __syncthreads();
        sums[t] += v;
        __syncthreads();
    }
    int run = (t == 0) ? 0 : sums[t - 1];
#pragma unroll
    for (int i = 0; i < per; i++) {
        int idx = base + i;
        if (idx < NN) {
            g_off[idx] = run;
            g_off2[idx] = run + idx;   // +1 self-loop slot per preceding node
            g_cnt[idx] = 0;            // zeroed here, before k_scatter
            run += g_deg[idx];
        }
    }
    if (t == 0) { g_off[NN] = NE; g_off2[NN] = NE + NN; }
}

__global__ void k_scatter(const int* __restrict__ ei) {
    int e = blockIdx.x * blockDim.x + threadIdx.x;
    if (e >= NE) return;
    int d = ei[NE + e];
    int pos = g_off[d] + atomicAdd(&g_cnt[d], 1);
    g_csr[pos] = e;
}

// Build item-ordered srcs + edge_attr (self-loop mean rows inlined).
// One warp per node: lanes 0-15 copy/accumulate edge_attr comps, lanes 16-31 srcs.
__global__ void k_build(const int* __restrict__ ei, const float* __restrict__ ea) {
    int wid = threadIdx.x >> 5;
    int lane = threadIdx.x & 31;
    int n = blockIdx.x * (blockDim.x >> 5) + wid;
    if (n >= NN) return;
    int off = g_off[n];
    int deg = g_off[n + 1] - off;
    int base = g_off2[n];

    if (lane < 16) {
        int c = lane;
        float sum = 0.f;
        int j = 0;
        for (; j + 1 < deg; j += 2) {
            int e0 = g_csr[off + j];
            int e1 = g_csr[off + j + 1];
            float v0 = ea[(size_t)e0 * ED + c];
            float v1 = ea[(size_t)e1 * ED + c];
            sum += v0 + v1;
            g_ea2[(size_t)(base + j) * ED + c] = v0;
            g_ea2[(size_t)(base + j + 1) * ED + c] = v1;
        }
        if (j < deg) {
            int e = g_csr[off + j];
            float v = ea[(size_t)e * ED + c];
            sum += v;
            g_ea2[(size_t)(base + j) * ED + c] = v;
        }
        float inv = (deg > 0) ? (1.f / (float)deg) : 1.f;
        g_ea2[(size_t)(base + deg) * ED + c] = sum * inv;   // self-loop row
    } else {
        int c = lane - 16;
        for (int j = c; j < deg; j += 16)
            g_srcs[base + j] = ei[g_csr[off + j]];
        if (c == 0) g_srcs[base + deg] = n;                 // self loop
    }
}

// ---------------- GEMM: C[M,320] = A[M,K] @ W[K,320] + bias ----------------
#define BM 128
#define BN 64
#define BK 16

__global__ void __launch_bounds__(256) k_gemm(
    const float* __restrict__ A, const float* __restrict__ W,
    const float* __restrict__ bias, float* __restrict__ C, int K)
{
    __shared__ float At[BK][BM + 4];
    __shared__ float Bs[BK][BN];
    const int tid = threadIdx.x;
    const int row0 = blockIdx.x * BM;
    const int col0 = blockIdx.y * BN;
    const int tx = tid & 15;   // N: 16 x 4
    const int ty = tid >> 4;   // M: 16 x 8

    float acc[8][4];
#pragma unroll
    for (int i = 0; i < 8; i++)
#pragma unroll
        for (int j = 0; j < 4; j++) acc[i][j] = 0.f;

    for (int k0 = 0; k0 < K; k0 += BK) {
#pragma unroll
        for (int i = 0; i < 2; i++) {
            int f = tid * 2 + i;
            int r = f >> 2;
            int kc = (f & 3) << 2;
            int gr = row0 + r;
            float4 v = make_float4(0.f, 0.f, 0.f, 0.f);
            if (gr < NN) v = *(const float4*)(A + (size_t)gr * K + k0 + kc);
            At[kc + 0][r] = v.x;
            At[kc + 1][r] = v.y;
            At[kc + 2][r] = v.z;
            At[kc + 3][r] = v.w;
        }
        {
            int k = tid >> 4;
            int c = (tid & 15) << 2;
            *(float4*)&Bs[k][c] = *(const float4*)(W + (size_t)(k0 + k) * HC + col0 + c);
        }
        __syncthreads();
#pragma unroll
        for (int k = 0; k < BK; k++) {
            float a[8], b[4];
            *(float4*)&a[0] = *(const float4*)&At[k][ty * 8];
            *(float4*)&a[4] = *(const float4*)&At[k][ty * 8 + 4];
            *(float4*)&b[0] = *(const float4*)&Bs[k][tx * 4];
#pragma unroll
            for (int i = 0; i < 8; i++)
#pragma unroll
                for (int j = 0; j < 4; j++)
                    acc[i][j] = fmaf(a[i], b[j], acc[i][j]);
        }
        __syncthreads();
    }

    float4 bv = *(const float4*)&bias[col0 + tx * 4];
#pragma unroll
    for (int i = 0; i < 8; i++) {
        int gr = row0 + ty * 8 + i;
        if (gr < NN) {
            float4 o;
            o.x = acc[i][0] + bv.x;
            o.y = acc[i][1] + bv.y;
            o.z = acc[i][2] + bv.z;
            o.w = acc[i][3] + bv.w;
            *(float4*)&C[(size_t)gr * HC + col0 + tx * 4] = o;
        }
    }
}

// ---------------- fused GATv2 layer v6 ----------------
// 160 threads = 5 warps = 1 node; warp h owns head h (2 comps/lane, packed f32x2).
// No pointer chase: g_srcs/g_ea2 are item-ordered, so staging a 32-item window
// is a 1-deep fully-coalesced copy by ALL 160 threads. Direct exp2 softmax.
__global__ void __launch_bounds__(160, 4) k_gat(
    const float* __restrict__ We, const float* __restrict__ att,
    const float* __restrict__ bias, float* __restrict__ out)
{
    const int tid = threadIdx.x;
    const int lane = tid & 31;
    const int h = tid >> 5;           // head = warp id (0..4)
    const int coff = h * 64 + 2 * lane;
    const unsigned FULL = 0xffffffffu;
    const float LOG2E = 1.4426950408889634f;

    const float attx = att[coff] * LOG2E;
    const float atty = att[coff + 1] * LOG2E;
    u64 We2[16];
#pragma unroll
    for (int kk = 0; kk < 8; kk++) {
        We2[kk]     = pk2(We[(2 * kk) * HC + coff],     We[(2 * kk + 1) * HC + coff]);
        We2[kk + 8] = pk2(We[(2 * kk) * HC + coff + 1], We[(2 * kk + 1) * HC + coff + 1]);
    }
    const u64 C02 = pk2(0.2f, 0.2f);

    __shared__ float s_red[5][64];
    __shared__ int s_src[32];
    __shared__ __align__(16) u64 s_ea[32][8];   // 2KB: 32 items x 64B edge_attr

    const int n = blockIdx.x;
    const u64 xld2 = *(const u64*)(g_xl + (size_t)n * HC + coff);
    const int base0 = g_off2[n];
    const int items = g_off2[n + 1] - base0;    // incoming edges + self loop

    float den = 0.f;
    u64 acc2 = pk2(0.f, 0.f);

    for (int base = 0; base < items; base += 32) {
        const int cnt = min(32, items - base);

        __syncthreads();   // s_ea/s_src safe to overwrite (no-op first window)
        {
            // parallel coalesced staging: 256 u64 among 160 threads (1-deep)
            const u64* g = (const u64*)g_ea2 + (size_t)(base0 + base) * 8;
            u64 v0 = g[tid];
            u64 v1 = (tid < 96) ? g[160 + tid] : 0ull;
            int sv = (tid < 32) ? g_srcs[base0 + base + tid] : 0;
            ((u64*)s_ea)[tid] = v0;
            if (tid < 96) ((u64*)s_ea)[160 + tid] = v1;
            if (tid < 32) s_src[tid] = sv;
        }
        __syncthreads();

        for (int g0 = 0; g0 < cnt; g0 += 8) {
            const int vcnt = min(8, cnt - g0);

            // --- 8 gathers in flight (clamped index for inactive slots) ---
            u64 xs2[8];
#pragma unroll
            for (int j = 0; j < 8; j++) {
                int s = s_src[min(g0 + j, cnt - 1)];
                xs2[j] = *(const u64*)(g_xl + (size_t)s * HC + coff);
            }

            // --- 8 scores ---
            float sc[8];
#pragma unroll
            for (int j = 0; j < 8; j++) {
                if (j < vcnt) {
                    const ulonglong2* q = (const ulonglong2*)s_ea[g0 + j];
                    ulonglong2 q0 = q[0], q1 = q[1], q2 = q[2], q3 = q[3];
                    u64 xsum = fadd2(xs2[j], xld2);
                    float sx, sy;
                    upk2(xsum, sx, sy);
                    u64 a0 = pk2(sx, 0.f);
                    u64 a1 = pk2(sy, 0.f);
                    a0 = ffma2(q0.x, We2[0], a0);  a1 = ffma2(q0.x, We2[8],  a1);
                    a0 = ffma2(q0.y, We2[1], a0);  a1 = ffma2(q0.y, We2[9],  a1);
                    a0 = ffma2(q1.x, We2[2], a0);  a1 = ffma2(q1.x, We2[10], a1);
                    a0 = ffma2(q1.y, We2[3], a0);  a1 = ffma2(q1.y, We2[11], a1);
                    a0 = ffma2(q2.x, We2[4], a0);  a1 = ffma2(q2.x, We2[12], a1);
                    a0 = ffma2(q2.y, We2[5], a0);  a1 = ffma2(q2.y, We2[13], a1);
                    a0 = ffma2(q3.x, We2[6], a0);  a1 = ffma2(q3.x, We2[14], a1);
                    a0 = ffma2(q3.y, We2[7], a0);  a1 = ffma2(q3.y, We2[15], a1);
                    float l0, h0, l1, h1;
                    upk2(a0, l0, h0);
                    upk2(a1, l1, h1);
                    float u0 = l0 + h0;
                    float u1 = l1 + h1;
                    u64 u5 = fmul2(pk2(u0, u1), C02);
                    float t0, t1;
                    upk2(u5, t0, t1);
                    float lr0 = fmaxf(u0, t0);
                    float lr1 = fmaxf(u1, t1);
                    sc[j] = fmaf(attx, lr0, atty * lr1);
                } else {
                    sc[j] = -1000.f;   // exp2 -> 0
                }
            }

            // --- 8 pipelined butterflies (identical sums on all lanes) ---
#pragma unroll
            for (int o = 16; o; o >>= 1) {
#pragma unroll
                for (int j = 0; j < 8; j++)
                    sc[j] += __shfl_xor_sync(FULL, sc[j], o);
            }

            // --- direct softmax accumulation (no max, no rescale) ---
#pragma unroll
            for (int j = 0; j < 8; j++) {
                float p = ex2f(fminf(sc[j], 100.f));
                den += p;
                acc2 = ffma2(pk2(p, p), xs2[j], acc2);
            }
        }
    }

    float invd = 1.f / den;
    float acc0, acc1;
    upk2(acc2, acc0, acc1);
    s_red[h][2 * lane]     = acc0 * invd;
    s_red[h][2 * lane + 1] = acc1 * invd;
    __syncthreads();

    if (tid < CD) {
        float o = (s_red[0][tid] + s_red[1][tid] + s_red[2][tid] +
                   s_red[3][tid] + s_red[4][tid]) * 0.2f + bias[tid];
        o = (o > 0.f) ? o : expm1f(o);  // ELU
        out[(size_t)n * CD + tid] = o;
    }
}

// ---------------- launcher ----------------
extern "C" void kernel_launch(void* const* d_in, const int* in_sizes, int n_in,
                              void* d_out, int out_size)
{
    const float* x = (const float*)d_in[0];
    const int* ei = (const int*)d_in[1];
    const float* ea = (const float*)d_in[2];
    const float *Wl[3], *bl[3], *We[3], *att[3], *bb[3];
    for (int l = 0; l < 3; l++) {
        Wl[l]  = (const float*)d_in[3 + l * 5 + 0];
        bl[l]  = (const float*)d_in[3 + l * 5 + 1];
        We[l]  = (const float*)d_in[3 + l * 5 + 2];
        att[l] = (const float*)d_in[3 + l * 5 + 3];
        bb[l]  = (const float*)d_in[3 + l * 5 + 4];
    }
    float* out = (float*)d_out;

    float *p_xl, *p_h1, *p_h2;
    cudaGetSymbolAddress((void**)&p_xl, g_xl);
    cudaGetSymbolAddress((void**)&p_h1, g_h1);
    cudaGetSymbolAddress((void**)&p_h2, g_h2);

    dim3 gg((NN + BM - 1) / BM, HC / BN);

    // preprocessing; layer-0 GEMM interleaved (independent of CSR build)
    k_init<<<(NN + 255) / 256, 256>>>();
    k_deg<<<(NE + 255) / 256, 256>>>(ei);
    k_scan<<<1, 1024>>>();
    k_gemm<<<gg, 256>>>(x, Wl[0], bl[0], p_xl, 128);   // layer 0 GEMM (K=128)
    k_scatter<<<(NE + 255) / 256, 256>>>(ei);
    k_build<<<(NN + 3) / 4, 128>>>(ei, ea);

    // layer 0
    k_gat<<<NN, 160>>>(We[0], att[0], bb[0], p_h1);
    // layer 1 (K=64)
    k_gemm<<<gg, 256>>>(p_h1, Wl[1], bl[1], p_xl, 64);
    k_gat<<<NN, 160>>>(We[1], att[1], bb[1], p_h2);
    // layer 2 (K=64)
    k_gemm<<<gg, 256>>>(p_h2, Wl[2], bl[2], p_xl, 64);
    k_gat<<<NN, 160>>>(We[2], att[2], bb[2], out);
}